// round 16
// baseline (speedup 1.0000x reference)
#include <cuda_runtime.h>
#include <cuda_fp16.h>
#include <math.h>
#include <stdint.h>

// Problem dims
#define T_DIM 512
#define B_DIM 32
#define E_DIM 512
#define H_DIM 2048

// Tiling: CTA = 128 thr, 4 warps (2M x 2N), warp tile 32x48, CTA tile 64x96
#define HC  32          // h channels per CTA
#define NT  96          // GEMM N
#define MT  64          // t-chunk (GEMM M)
#define KC  32          // K per smem chunk (fp16 -> 64B rows, SW64)
#define NKC 16          // K chunks per t-chunk
#define NTC 8           // t-chunks
#define NCH (NTC * NKC) // 128 chunks

#define ASTR 108        // act row stride in BYTES (16*108 % 128 == 64: conflict-free seg rows)

// ---- smem layout (bytes) ----
#define SM_A    0                    // 2 x 4096  (A stages, fp16 SW64)
#define SM_B    8192                 // 2 x 6144  (W stages, fp16 SW64, permuted)
#define SM_ACT  20480                // 4 warps x 32 rows x 108B = 13824
#define SM_BIAS 34304                // half2 bias tables [3 grp][2 wn][8 pr] = 192B
#define SM_SEGA 34560                // [2 par][2 wn][2 wm][16] floats = 512
#define SM_SEGB 35072                // 512
#define SMEM_BYTES 35584             // x5 CTAs = 177920 <= 228KB

#define SWZ64(x) ((x) ^ (((x) >> 3) & 0x30))

// fp16 scratch (static device allocations — allowed)
__device__ __half g_sentH[B_DIM * T_DIM * E_DIM];   // (B,T,E) fp16
__device__ __half g_wH[3 * H_DIM * E_DIM];          // (3H,E)  fp16

// ---------------- helpers ----------------
__device__ __forceinline__ uint32_t smem_u32(const void* p) {
    uint32_t a;
    asm("{ .reg .u64 t; cvta.to.shared.u64 t, %1; cvt.u32.u64 %0, t; }" : "=r"(a) : "l"(p));
    return a;
}
__device__ __forceinline__ __half2 h2tanh_hw(__half2 x) {
    uint32_t xi = *(uint32_t*)&x, yi;
    asm("tanh.approx.f16x2 %0, %1;" : "=r"(yi) : "r"(xi));
    return *(__half2*)&yi;
}
__device__ __forceinline__ void cp_async16(uint32_t dst, const void* src) {
    uint64_t g; asm("cvta.to.global.u64 %0, %1;" : "=l"(g) : "l"(src));
    asm volatile("cp.async.cg.shared.global [%0], [%1], 16;" :: "r"(dst), "l"(g) : "memory");
}
__device__ __forceinline__ void ldsm4(uint32_t* r, uint32_t addr) {
    asm volatile("ldmatrix.sync.aligned.m8n8.x4.shared.b16 {%0,%1,%2,%3}, [%4];"
                 : "=r"(r[0]), "=r"(r[1]), "=r"(r[2]), "=r"(r[3]) : "r"(addr));
}
__device__ __forceinline__ void mma_f16(float* c, const uint32_t* a, const uint32_t* b) {
    asm volatile(
        "mma.sync.aligned.m16n8k16.row.col.f32.f16.f16.f32 "
        "{%0,%1,%2,%3}, {%4,%5,%6,%7}, {%8,%9}, {%0,%1,%2,%3};"
        : "+f"(c[0]), "+f"(c[1]), "+f"(c[2]), "+f"(c[3])
        : "r"(a[0]), "r"(a[1]), "r"(a[2]), "r"(a[3]), "r"(b[0]), "r"(b[1]));
}

// ---------- merged prepass: fp32 -> fp16; sent also transposed (T,B,E)->(B,T,E) ----------
#define SENT_F4 (T_DIM * B_DIM * E_DIM / 4)   // 2,097,152
#define W_F4    (3 * H_DIM * E_DIM / 4)       //   786,432
__global__ void __launch_bounds__(256) prep_all(const float* __restrict__ sent,
                                                const float* __restrict__ W) {
    int li = blockIdx.x * 256 + threadIdx.x;
    if (li < SENT_F4) {
        const float4 v = ((const float4*)sent)[li];
        int e4 = li & 127;
        int b  = (li >> 7) & 31;
        int t  = li >> 12;
        __half2* dst = (__half2*)(g_sentH + ((size_t)(b * T_DIM + t) * E_DIM + e4 * 4));
        dst[0] = __floats2half2_rn(v.x, v.y);
        dst[1] = __floats2half2_rn(v.z, v.w);
    } else if (li < SENT_F4 + W_F4) {
        int wi = li - SENT_F4;
        const float4 v = ((const float4*)W)[wi];
        __half2* dst = (__half2*)g_wH + (size_t)wi * 2;
        dst[0] = __floats2half2_rn(v.x, v.y);
        dst[1] = __floats2half2_rn(v.z, v.w);
    }
}

// -------- fused kernel: 128 thr, 4 warps 2M x 2N, warp tile 32x48, occ 5 --------
// W permuted so N-half wn owns z|f|o of channels [16*wn, 16*wn+16):
//   staged row n -> wn = n/48, r = n%48, grp = r/16, c = r%16
//               -> physical W row grp*H_DIM + h0 + wn*16 + c
// Warp (wm, wn) owns t-rows [32*wm,+32) x channels [16*wn,+16) -> warp-local
// epilogue + scan; only the 2-segment carry crosses warps (tiny smem table).
__global__ void __launch_bounds__(128, 5)
qrnn_f16_kernel(const float* __restrict__ bias, float* __restrict__ out)
{
    extern __shared__ char smem[];
    const uint32_t sb = smem_u32(smem);
    const int tid = threadIdx.x;
    const int bb  = blockIdx.y;
    const int h0  = blockIdx.x * HC;
    const int lane = tid & 31;
    const int wid  = tid >> 5;
    const int g  = lane >> 2;
    const int tg = lane & 3;
    const int wm = wid & 1;          // M half (t)
    const int wn = wid >> 1;         // N half (channels)
    const int m_base = wm * 32;
    const int n_base = wn * 48;

    __half2* sbh2 = (__half2*)(smem + SM_BIAS);           // [grp][wn][pr]
    char*  actw   = smem + SM_ACT + wid * (32 * ASTR);    // warp-private 32 rows
    float* segA   = (float*)(smem + SM_SEGA);             // [par][wn][wm][16]
    float* segB   = (float*)(smem + SM_SEGB);
    if (tid < 48) {
        int wn_i = tid / 24;
        int r    = tid % 24;
        int grp  = r >> 3;
        int pr   = r & 7;
        int c0   = h0 + wn_i * 16 + pr * 2;
        float b0 = bias[grp * H_DIM + c0];
        float b1 = bias[grp * H_DIM + c0 + 1];
        float s  = (grp == 0) ? 1.0f : 0.5f;     // f/o inputs pre-scaled by 0.5
        sbh2[grp * 16 + wn_i * 8 + pr] = __floats2half2_rn(s * b0, s * b1);
    }

    const __half* Asrc = g_sentH + (size_t)bb * (T_DIM * E_DIM);

    // ldmatrix lane->address components
    const int am = lane >> 3;
    const int a_row_in = (am & 1) * 8 + (lane & 7);
    const int a_colb16 = (am >> 1) * 16;
    const int b_row_in = (am >> 1) * 8 + (lane & 7);
    const int b_colb16 = (am & 1) * 16;

    auto stage = [&](int ch) {
        const int tc = ch >> 4, kc = ch & 15, buf = ch & 1;
        const __half* ab = Asrc + (size_t)(tc * MT) * E_DIM + kc * KC;
        const uint32_t aB = sb + SM_A + buf * 4096;
#pragma unroll
        for (int i = 0; i < 2; i++) {                 // A: 64 rows x 64B = 256 x 16B
            int l = i * 128 + tid;
            int row = l >> 2, c = l & 3;
            cp_async16(aB + (uint32_t)SWZ64(row * 64 + c * 16), ab + (size_t)row * E_DIM + c * 8);
        }
        const uint32_t bB = sb + SM_B + buf * 6144;
#pragma unroll
        for (int i = 0; i < 3; i++) {                 // B: 96 rows x 64B = 384 x 16B
            int l = i * 128 + tid;
            int n = l >> 2, c = l & 3;
            int w = (n >= 48) ? 1 : 0;
            int r = n - w * 48;
            int wrow = (r >> 4) * H_DIM + h0 + w * 16 + (r & 15);
            cp_async16(bB + (uint32_t)SWZ64(n * 64 + c * 16),
                       g_wH + (size_t)wrow * E_DIM + kc * KC + c * 8);
        }
        asm volatile("cp.async.commit_group;" ::: "memory");
    };

    // scan lanes: s_id = lane>>4 (16-t segment within the warp's 32 t), chn = lane&15
    const int s_id = lane >> 4;
    const int chn  = lane & 15;
    float c_carry = 0.0f;              // replicated across warps (identical math)
    float m_state = -INFINITY;

    stage(0);

    for (int tc = 0; tc < NTC; tc++) {
        const int par = tc & 1;
        float acc[2][6][4];
#pragma unroll
        for (int mf = 0; mf < 2; mf++)
#pragma unroll
            for (int nf = 0; nf < 6; nf++)
#pragma unroll
                for (int q = 0; q < 4; q++) acc[mf][nf][q] = 0.0f;

        for (int kc = 0; kc < NKC; kc++) {
            const int ch  = tc * NKC + kc;
            const int buf = ch & 1;

            asm volatile("cp.async.wait_group 0;" ::: "memory");
            __syncthreads();   // chunk ch visible; chunk ch-1's readers done
            if (ch + 1 < NCH) stage(ch + 1);   // fill alt buffer; overlaps MMAs

            const uint32_t aB = sb + SM_A + buf * 4096;
            const uint32_t bB = sb + SM_B + buf * 6144;
#pragma unroll
            for (int ks = 0; ks < 2; ks++) {     // 2 k16-steps over KC=32
                uint32_t a[2][4];
#pragma unroll
                for (int mf = 0; mf < 2; mf++)
                    ldsm4(a[mf], aB + (uint32_t)SWZ64((m_base + mf * 16 + a_row_in) * 64
                                                      + ks * 32 + a_colb16));
                uint32_t b[6][2];
#pragma unroll
                for (int p = 0; p < 3; p++) {
                    uint32_t r[4];
                    ldsm4(r, bB + (uint32_t)SWZ64((n_base + p * 16 + b_row_in) * 64
                                                  + ks * 32 + b_colb16));
                    b[2 * p][0] = r[0];     b[2 * p][1] = r[1];
                    b[2 * p + 1][0] = r[2]; b[2 * p + 1][1] = r[3];
                }
#pragma unroll
                for (int mf = 0; mf < 2; mf++)
#pragma unroll
                    for (int nf = 0; nf < 6; nf++)
                        mma_f16(acc[mf][nf], a[mf], b[nf]);
            }
        }

        // ---- epilogue (warp-local, f16x2 path): zf interleaved, o planar pairs ----
        // tanh/sigmoid in half2: sig(x) = 0.5*tanh(0.5x) + 0.5; f/o bias pre-scaled.
        {
            const __half2 h05 = __float2half2_rn(0.5f);
#pragma unroll
            for (int mf = 0; mf < 2; mf++) {
#pragma unroll
                for (int nf01 = 0; nf01 < 2; nf01++) {
                    int pr = nf01 * 4 + tg;          // pair index 0..7
                    int cp = pr * 2;                 // channel (even)
                    __half2 bz = sbh2[wn * 8 + pr];
                    __half2 bf = sbh2[16 + wn * 8 + pr];
                    __half2 bo = sbh2[32 + wn * 8 + pr];
#pragma unroll
                    for (int rr = 0; rr < 2; rr++) {
                        int row = mf * 16 + rr * 8 + g;   // local t row 0..31
                        int q   = rr * 2;
                        __half2 zt = h2tanh_hw(__hadd2(
                            __floats2half2_rn(acc[mf][nf01][q], acc[mf][nf01][q + 1]), bz));
                        __half2 ft = __hfma2(h2tanh_hw(__hfma2(
                            __floats2half2_rn(acc[mf][nf01 + 2][q], acc[mf][nf01 + 2][q + 1]),
                            h05, bf)), h05, h05);
                        __half2 ot = __hfma2(h2tanh_hw(__hfma2(
                            __floats2half2_rn(acc[mf][nf01 + 4][q], acc[mf][nf01 + 4][q + 1]),
                            h05, bo)), h05, h05);
                        char* rp = actw + row * ASTR;
                        *(__half2*)(rp + cp * 4)      = __halves2half2(__low2half(zt),  __low2half(ft));
                        *(__half2*)(rp + cp * 4 + 4)  = __halves2half2(__high2half(zt), __high2half(ft));
                        *(__half2*)(rp + 64 + cp * 2) = ot;
                    }
                }
            }
        }
        __syncwarp();

        // ---- scan pass 1: per-lane 16-t segment affine (A,B) ----
        float A = 1.0f, B = 0.0f;
#pragma unroll
        for (int i = 0; i < 16; i++) {
            const char* rp = actw + (s_id * 16 + i) * ASTR;
            __half2 zf = *(const __half2*)(rp + chn * 4);
            float z = __half2float(__low2half(zf));
            float f = __half2float(__high2half(zf));
            float a_ = 1.0f - f;
            A *= a_;
            B = fmaf(a_, B, f * z);
        }
        // seg0 values (for s1 entry) and warp total (on s1 lanes)
        float As0 = __shfl_sync(0xffffffffu, A, chn);
        float Bs0 = __shfl_sync(0xffffffffu, B, chn);
        {
            float Au = __shfl_up_sync(0xffffffffu, A, 16);
            float Bu = __shfl_up_sync(0xffffffffu, B, 16);
            if (lane >= 16) { B = fmaf(A, Bu, B); A *= Au; }   // warp 32-t total on s1
        }
        if (lane >= 16) {
            segA[par * 64 + wn * 32 + wm * 16 + chn] = A;
            segB[par * 64 + wn * 32 + wm * 16 + chn] = B;
        }
        __syncthreads();

        // warp entry state, then lane entry state
        float A0 = segA[par * 64 + wn * 32 + chn];
        float B0 = segB[par * 64 + wn * 32 + chn];
        float e  = (wm == 0) ? c_carry : fmaf(A0, c_carry, B0);
        float c  = (s_id == 0) ? e : fmaf(As0, e, Bs0);

        // ---- scan pass 2: walk my 16 t's with running max of o*c ----
#pragma unroll
        for (int i = 0; i < 16; i++) {
            const char* rp = actw + (s_id * 16 + i) * ASTR;
            __half2 zf = *(const __half2*)(rp + chn * 4);
            float z = __half2float(__low2half(zf));
            float f = __half2float(__high2half(zf));
            float o = __half2float(*(const __half*)(rp + 64 + chn * 2));
            c = fmaf(f, z - c, c);                 // c = f*z + (1-f)*c
            m_state = fmaxf(m_state, o * c);
        }
        // carry advance over the whole 64-t chunk (replicated in all warps)
        {
            float A1 = segA[par * 64 + wn * 32 + 16 + chn];
            float B1 = segB[par * 64 + wn * 32 + 16 + chn];
            c_carry = fmaf(A1, fmaf(A0, c_carry, B0), B1);
        }
        // next same-parity table write is 2 t-chunks away (>=16 chunk syncs) — safe
    }

    // ---- final max: across s lanes, then across wm halves ----
    m_state = fmaxf(m_state, __shfl_xor_sync(0xffffffffu, m_state, 16));
    __syncthreads();                       // seg tables free for reuse
    float* mt = segA;                      // [wn][wm][16]
    if (lane < 16) mt[wn * 32 + wm * 16 + chn] = m_state;
    __syncthreads();
    if (wm == 0 && lane < 16) {
        float r = fmaxf(m_state, mt[wn * 32 + 16 + chn]);
        out[bb * H_DIM + h0 + wn * 16 + chn] = r;
    }
}

extern "C" void kernel_launch(void* const* d_in, const int* in_sizes, int n_in,
                              void* d_out, int out_size)
{
    (void)in_sizes; (void)n_in; (void)out_size;
    const float* sent = (const float*)d_in[0];   // (T,B,E) fp32
    const float* W    = (const float*)d_in[2];   // (3H,E)  fp32
    const float* bias = (const float*)d_in[3];   // (3H)    fp32
    float* out = (float*)d_out;                  // (B,H)   fp32

    cudaFuncSetAttribute(qrnn_f16_kernel, cudaFuncAttributeMaxDynamicSharedMemorySize, SMEM_BYTES);

    prep_all<<<(SENT_F4 + W_F4 + 255) / 256, 256>>>(sent, W);
    qrnn_f16_kernel<<<dim3(H_DIM / HC, B_DIM), 128, SMEM_BYTES>>>(bias, out);
}

// round 17
// speedup vs baseline: 1.2153x; 1.2153x over previous
#include <cuda_runtime.h>
#include <cuda_fp16.h>
#include <math.h>
#include <stdint.h>

// Problem dims
#define T_DIM 512
#define B_DIM 32
#define E_DIM 512
#define H_DIM 2048

// Tiling: CTA = 128 thr, 4 warps (2M x 2N), warp tile 32x48, CTA tile 64x96
#define HC  32          // h channels per CTA
#define NT  96          // GEMM N
#define MT  64          // t-chunk (GEMM M)
#define KC  64          // K per smem chunk (fp16 -> 128B rows)
#define NKC 8           // K chunks per t-chunk
#define NTC 8           // t-chunks
#define NCH (NTC * NKC) // 64 chunks

#define ASTR 108        // act row stride in BYTES (16*108 % 128 == 64: conflict-free seg rows)

// ---- smem layout (bytes) ----
#define SM_A    0                    // 2 x 8192   (A stages, fp16 SW128)
#define SM_B    16384                // 2 x 12288  (W stages, fp16 SW128, permuted)
#define SM_ACT  40960                // 4 warps x 32 rows x 108B = 13824
#define SM_BIAS 54784                // half2 bias tables [3 grp][2 wn][8 pr] = 192B
#define SM_SEGA 55168                // [2 par][2 wn][2 wm][16] floats = 512
#define SM_SEGB 55680                // 512
#define SMEM_BYTES 56192             // x4 CTAs = 224768 <= 228KB

#define SWZ128(x) ((x) ^ (((x) >> 3) & 0x70))

// fp16 scratch (static device allocations — allowed)
__device__ __half g_sentH[B_DIM * T_DIM * E_DIM];   // (B,T,E) fp16
__device__ __half g_wH[3 * H_DIM * E_DIM];          // (3H,E)  fp16

// ---------------- helpers ----------------
__device__ __forceinline__ uint32_t smem_u32(const void* p) {
    uint32_t a;
    asm("{ .reg .u64 t; cvta.to.shared.u64 t, %1; cvt.u32.u64 %0, t; }" : "=r"(a) : "l"(p));
    return a;
}
__device__ __forceinline__ __half2 h2tanh_hw(__half2 x) {
    uint32_t xi = *(uint32_t*)&x, yi;
    asm("tanh.approx.f16x2 %0, %1;" : "=r"(yi) : "r"(xi));
    return *(__half2*)&yi;
}
__device__ __forceinline__ void cp_async16(uint32_t dst, const void* src) {
    uint64_t g; asm("cvta.to.global.u64 %0, %1;" : "=l"(g) : "l"(src));
    asm volatile("cp.async.cg.shared.global [%0], [%1], 16;" :: "r"(dst), "l"(g) : "memory");
}
__device__ __forceinline__ void ldsm4(uint32_t* r, uint32_t addr) {
    asm volatile("ldmatrix.sync.aligned.m8n8.x4.shared.b16 {%0,%1,%2,%3}, [%4];"
                 : "=r"(r[0]), "=r"(r[1]), "=r"(r[2]), "=r"(r[3]) : "r"(addr));
}
__device__ __forceinline__ void mma_f16(float* c, const uint32_t* a, const uint32_t* b) {
    asm volatile(
        "mma.sync.aligned.m16n8k16.row.col.f32.f16.f16.f32 "
        "{%0,%1,%2,%3}, {%4,%5,%6,%7}, {%8,%9}, {%0,%1,%2,%3};"
        : "+f"(c[0]), "+f"(c[1]), "+f"(c[2]), "+f"(c[3])
        : "r"(a[0]), "r"(a[1]), "r"(a[2]), "r"(a[3]), "r"(b[0]), "r"(b[1]));
}

// ---------- merged prepass: fp32 -> fp16; sent also transposed (T,B,E)->(B,T,E) ----------
// 2 independent float4s per thread (MLP=2) to raise DRAM utilization.
#define SENT_F4 (T_DIM * B_DIM * E_DIM / 4)   // 2,097,152
#define W_F4    (3 * H_DIM * E_DIM / 4)       //   786,432
#define PREP_TOT (SENT_F4 + W_F4)             // 2,883,584
__global__ void __launch_bounds__(256) prep_all(const float* __restrict__ sent,
                                                const float* __restrict__ W) {
    int base = blockIdx.x * 512 + threadIdx.x;
#pragma unroll
    for (int rep = 0; rep < 2; rep++) {
        int li = base + rep * 256;
        if (li < SENT_F4) {
            const float4 v = ((const float4*)sent)[li];
            int e4 = li & 127;
            int b  = (li >> 7) & 31;
            int t  = li >> 12;
            __half2* dst = (__half2*)(g_sentH + ((size_t)(b * T_DIM + t) * E_DIM + e4 * 4));
            dst[0] = __floats2half2_rn(v.x, v.y);
            dst[1] = __floats2half2_rn(v.z, v.w);
        } else if (li < PREP_TOT) {
            int wi = li - SENT_F4;
            const float4 v = ((const float4*)W)[wi];
            __half2* dst = (__half2*)g_wH + (size_t)wi * 2;
            dst[0] = __floats2half2_rn(v.x, v.y);
            dst[1] = __floats2half2_rn(v.z, v.w);
        }
    }
}

// -------- fused kernel: 128 thr, 4 warps 2M x 2N, warp tile 32x48, occ 4 --------
// W permuted so N-half wn owns z|f|o of channels [16*wn, 16*wn+16):
//   staged row n -> wn = n/48, r = n%48, grp = r/16, c = r%16
//               -> physical W row grp*H_DIM + h0 + wn*16 + c
// Warp (wm, wn) owns t-rows [32*wm,+32) x channels [16*wn,+16) -> warp-local
// epilogue + scan; only the 2-segment carry crosses warps (tiny smem table).
__global__ void __launch_bounds__(128, 4)
qrnn_f16_kernel(const float* __restrict__ bias, float* __restrict__ out)
{
    extern __shared__ char smem[];
    const uint32_t sb = smem_u32(smem);
    const int tid = threadIdx.x;
    const int bb  = blockIdx.y;
    const int h0  = blockIdx.x * HC;
    const int lane = tid & 31;
    const int wid  = tid >> 5;
    const int g  = lane >> 2;
    const int tg = lane & 3;
    const int wm = wid & 1;          // M half (t)
    const int wn = wid >> 1;         // N half (channels)
    const int m_base = wm * 32;
    const int n_base = wn * 48;

    __half2* sbh2 = (__half2*)(smem + SM_BIAS);           // [grp][wn][pr]
    char*  actw   = smem + SM_ACT + wid * (32 * ASTR);    // warp-private 32 rows
    float* segA   = (float*)(smem + SM_SEGA);             // [par][wn][wm][16]
    float* segB   = (float*)(smem + SM_SEGB);
    if (tid < 48) {
        int wn_i = tid / 24;
        int r    = tid % 24;
        int grp  = r >> 3;
        int pr   = r & 7;
        int c0   = h0 + wn_i * 16 + pr * 2;
        float b0 = bias[grp * H_DIM + c0];
        float b1 = bias[grp * H_DIM + c0 + 1];
        float s  = (grp == 0) ? 1.0f : 0.5f;     // f/o inputs pre-scaled by 0.5
        sbh2[grp * 16 + wn_i * 8 + pr] = __floats2half2_rn(s * b0, s * b1);
    }

    const __half* Asrc = g_sentH + (size_t)bb * (T_DIM * E_DIM);

    // ldmatrix lane->address components
    const int am = lane >> 3;
    const int a_row_in = (am & 1) * 8 + (lane & 7);
    const int a_colb16 = (am >> 1) * 16;
    const int b_row_in = (am >> 1) * 8 + (lane & 7);
    const int b_colb16 = (am & 1) * 16;

    auto stage = [&](int ch) {
        const int tc = ch >> 3, kc = ch & 7, buf = ch & 1;
        const __half* ab = Asrc + (size_t)(tc * MT) * E_DIM + kc * KC;
        const uint32_t aB = sb + SM_A + buf * 8192;
#pragma unroll
        for (int i = 0; i < 4; i++) {                 // A: 64 rows x 128B = 512 x 16B
            int l = i * 128 + tid;
            int row = l >> 3, c = l & 7;
            cp_async16(aB + (uint32_t)SWZ128(row * 128 + c * 16), ab + (size_t)row * E_DIM + c * 8);
        }
        const uint32_t bB = sb + SM_B + buf * 12288;
#pragma unroll
        for (int i = 0; i < 6; i++) {                 // B: 96 rows x 128B = 768 x 16B
            int l = i * 128 + tid;
            int n = l >> 3, c = l & 7;
            int w = (n >= 48) ? 1 : 0;
            int r = n - w * 48;
            int wrow = (r >> 4) * H_DIM + h0 + w * 16 + (r & 15);
            cp_async16(bB + (uint32_t)SWZ128(n * 128 + c * 16),
                       g_wH + (size_t)wrow * E_DIM + kc * KC + c * 8);
        }
        asm volatile("cp.async.commit_group;" ::: "memory");
    };

    // scan lanes: s_id = lane>>4 (16-t segment within the warp's 32 t), chn = lane&15
    const int s_id = lane >> 4;
    const int chn  = lane & 15;
    float c_carry = 0.0f;              // replicated across warps (identical math)
    float m_state = -INFINITY;

    stage(0);

    for (int tc = 0; tc < NTC; tc++) {
        const int par = tc & 1;
        float acc[2][6][4];
#pragma unroll
        for (int mf = 0; mf < 2; mf++)
#pragma unroll
            for (int nf = 0; nf < 6; nf++)
#pragma unroll
                for (int q = 0; q < 4; q++) acc[mf][nf][q] = 0.0f;

        for (int kc = 0; kc < NKC; kc++) {
            const int ch  = tc * NKC + kc;
            const int buf = ch & 1;

            asm volatile("cp.async.wait_group 0;" ::: "memory");
            __syncthreads();   // chunk ch visible; chunk ch-1's readers done
            if (ch + 1 < NCH) stage(ch + 1);   // fill alt buffer; overlaps MMAs

            const uint32_t aB = sb + SM_A + buf * 8192;
            const uint32_t bB = sb + SM_B + buf * 12288;
#pragma unroll
            for (int ks = 0; ks < 4; ks++) {     // 4 k16-steps over KC=64
                uint32_t a[2][4];
#pragma unroll
                for (int mf = 0; mf < 2; mf++)
                    ldsm4(a[mf], aB + (uint32_t)SWZ128((m_base + mf * 16 + a_row_in) * 128
                                                       + ks * 32 + a_colb16));
                uint32_t b[6][2];
#pragma unroll
                for (int p = 0; p < 3; p++) {
                    uint32_t r[4];
                    ldsm4(r, bB + (uint32_t)SWZ128((n_base + p * 16 + b_row_in) * 128
                                                   + ks * 32 + b_colb16));
                    b[2 * p][0] = r[0];     b[2 * p][1] = r[1];
                    b[2 * p + 1][0] = r[2]; b[2 * p + 1][1] = r[3];
                }
#pragma unroll
                for (int mf = 0; mf < 2; mf++)
#pragma unroll
                    for (int nf = 0; nf < 6; nf++)
                        mma_f16(acc[mf][nf], a[mf], b[nf]);
            }
        }

        // ---- epilogue (warp-local, f16x2 path): zf interleaved, o planar pairs ----
        // tanh/sigmoid in half2: sig(x) = 0.5*tanh(0.5x) + 0.5; f/o bias pre-scaled.
        {
            const __half2 h05 = __float2half2_rn(0.5f);
#pragma unroll
            for (int mf = 0; mf < 2; mf++) {
#pragma unroll
                for (int nf01 = 0; nf01 < 2; nf01++) {
                    int pr = nf01 * 4 + tg;          // pair index 0..7
                    int cp = pr * 2;                 // channel (even)
                    __half2 bz = sbh2[wn * 8 + pr];
                    __half2 bf = sbh2[16 + wn * 8 + pr];
                    __half2 bo = sbh2[32 + wn * 8 + pr];
#pragma unroll
                    for (int rr = 0; rr < 2; rr++) {
                        int row = mf * 16 + rr * 8 + g;   // local t row 0..31
                        int q   = rr * 2;
                        __half2 zt = h2tanh_hw(__hadd2(
                            __floats2half2_rn(acc[mf][nf01][q], acc[mf][nf01][q + 1]), bz));
                        __half2 ft = __hfma2(h2tanh_hw(__hfma2(
                            __floats2half2_rn(acc[mf][nf01 + 2][q], acc[mf][nf01 + 2][q + 1]),
                            h05, bf)), h05, h05);
                        __half2 ot = __hfma2(h2tanh_hw(__hfma2(
                            __floats2half2_rn(acc[mf][nf01 + 4][q], acc[mf][nf01 + 4][q + 1]),
                            h05, bo)), h05, h05);
                        char* rp = actw + row * ASTR;
                        *(__half2*)(rp + cp * 4)      = __halves2half2(__low2half(zt),  __low2half(ft));
                        *(__half2*)(rp + cp * 4 + 4)  = __halves2half2(__high2half(zt), __high2half(ft));
                        *(__half2*)(rp + 64 + cp * 2) = ot;
                    }
                }
            }
        }
        __syncwarp();

        // ---- scan pass 1: per-lane 16-t segment affine (A,B) ----
        float A = 1.0f, B = 0.0f;
#pragma unroll
        for (int i = 0; i < 16; i++) {
            const char* rp = actw + (s_id * 16 + i) * ASTR;
            __half2 zf = *(const __half2*)(rp + chn * 4);
            float z = __half2float(__low2half(zf));
            float f = __half2float(__high2half(zf));
            float a_ = 1.0f - f;
            A *= a_;
            B = fmaf(a_, B, f * z);
        }
        // seg0 values (for s1 entry) and warp total (on s1 lanes)
        float As0 = __shfl_sync(0xffffffffu, A, chn);
        float Bs0 = __shfl_sync(0xffffffffu, B, chn);
        {
            float Au = __shfl_up_sync(0xffffffffu, A, 16);
            float Bu = __shfl_up_sync(0xffffffffu, B, 16);
            if (lane >= 16) { B = fmaf(A, Bu, B); A *= Au; }   // warp 32-t total on s1
        }
        if (lane >= 16) {
            segA[par * 64 + wn * 32 + wm * 16 + chn] = A;
            segB[par * 64 + wn * 32 + wm * 16 + chn] = B;
        }
        __syncthreads();

        // warp entry state, then lane entry state
        float A0 = segA[par * 64 + wn * 32 + chn];
        float B0 = segB[par * 64 + wn * 32 + chn];
        float e  = (wm == 0) ? c_carry : fmaf(A0, c_carry, B0);
        float c  = (s_id == 0) ? e : fmaf(As0, e, Bs0);

        // ---- scan pass 2: walk my 16 t's with running max of o*c ----
#pragma unroll
        for (int i = 0; i < 16; i++) {
            const char* rp = actw + (s_id * 16 + i) * ASTR;
            __half2 zf = *(const __half2*)(rp + chn * 4);
            float z = __half2float(__low2half(zf));
            float f = __half2float(__high2half(zf));
            float o = __half2float(*(const __half*)(rp + 64 + chn * 2));
            c = fmaf(f, z - c, c);                 // c = f*z + (1-f)*c
            m_state = fmaxf(m_state, o * c);
        }
        // carry advance over the whole 64-t chunk (replicated in all warps)
        {
            float A1 = segA[par * 64 + wn * 32 + 16 + chn];
            float B1 = segB[par * 64 + wn * 32 + 16 + chn];
            c_carry = fmaf(A1, fmaf(A0, c_carry, B0), B1);
        }
        // next same-parity table write is 2 t-chunks away (>=8 chunk syncs) — safe
    }

    // ---- final max: across s lanes, then across wm halves ----
    m_state = fmaxf(m_state, __shfl_xor_sync(0xffffffffu, m_state, 16));
    __syncthreads();                       // seg tables free for reuse
    float* mt = segA;                      // [wn][wm][16]
    if (lane < 16) mt[wn * 32 + wm * 16 + chn] = m_state;
    __syncthreads();
    if (wm == 0 && lane < 16) {
        float r = fmaxf(m_state, mt[wn * 32 + 16 + chn]);
        out[bb * H_DIM + h0 + wn * 16 + chn] = r;
    }
}

extern "C" void kernel_launch(void* const* d_in, const int* in_sizes, int n_in,
                              void* d_out, int out_size)
{
    (void)in_sizes; (void)n_in; (void)out_size;
    const float* sent = (const float*)d_in[0];   // (T,B,E) fp32
    const float* W    = (const float*)d_in[2];   // (3H,E)  fp32
    const float* bias = (const float*)d_in[3];   // (3H)    fp32
    float* out = (float*)d_out;                  // (B,H)   fp32

    cudaFuncSetAttribute(qrnn_f16_kernel, cudaFuncAttributeMaxDynamicSharedMemorySize, SMEM_BYTES);

    prep_all<<<(PREP_TOT + 511) / 512, 256>>>(sent, W);
    qrnn_f16_kernel<<<dim3(H_DIM / HC, B_DIM), 128, SMEM_BYTES>>>(bias, out);
}